// round 12
// baseline (speedup 1.0000x reference)
#include <cuda_runtime.h>
#include <cuda_bf16.h>
#include <math.h>
#include <stdint.h>

#define NSEQ  256     // B*S
#define TSEQ  128
#define EMBED 512
#define UNITS 512
#define G4    2048    // 4*UNITS
#define KDIM  512
#define KC    64      // k-chunk (bf16 elems) = 128B row
#define NCHUNK 8
#define NCTA  128     // persistent grid size

// ---------------- scratch (__device__ globals, allocation-free) ----------------
__device__ __align__(16) float g_xW[2][TSEQ][NSEQ][G4];               // 512 MB
__device__ __align__(16) __nv_bfloat16 g_hbf[2][2][2][NSEQ][UNITS];   // h hi/lo, dbl-buf
__device__ __align__(16) __nv_bfloat16 g_Ubf[2][2][G4][KDIM];         // U hi/lo, permuted
__device__ __align__(16) __nv_bfloat16 g_Wbf[2][2][G4][KDIM];         // W hi/lo, natural
__device__ __align__(16) __nv_bfloat16 g_xE[2][NSEQ * TSEQ][EMBED];   // emb hi/lo, 64 MB
__device__ __align__(16) float g_c[2][2][NSEQ][UNITS];
__device__ unsigned g_bar_cnt;                                        // start/exit barrier
__device__ int g_Wf[2][2][32];    // write flags: epilogues done (value = t+1)
__device__ int g_Rf[2][2][32];    // read  flags: A-chunks staged  (value = t)

// ---------------- helpers ----------------
__device__ __forceinline__ uint32_t smem_u32(const void* p) {
    uint32_t a;
    asm("{ .reg .u64 t; cvta.to.shared.u64 t, %1; cvt.u32.u64 %0, t; }" : "=r"(a) : "l"(p));
    return a;
}
__device__ __forceinline__ int ld_acq(const int* p) {
    int v;
    asm volatile("ld.acquire.gpu.global.b32 %0, [%1];" : "=r"(v) : "l"(p) : "memory");
    return v;
}
__device__ __forceinline__ void st_rel(int* p, int v) {
    asm volatile("st.release.gpu.global.b32 [%0], %1;" :: "l"(p), "r"(v) : "memory");
}
#define SWZ(r, kb) (((r) * 128) + ((kb) ^ (((r) & 7) << 4)))

#define LDSM_X4(r0, r1, r2, r3, addr) \
    asm volatile("ldmatrix.sync.aligned.m8n8.x4.shared.b16 {%0,%1,%2,%3}, [%4];" \
        : "=r"(r0), "=r"(r1), "=r"(r2), "=r"(r3) : "r"(addr))

#define MMA16816(d, a, b0, b1) \
    asm volatile("mma.sync.aligned.m16n8k16.row.col.f32.bf16.bf16.f32 " \
        "{%0,%1,%2,%3}, {%4,%5,%6,%7}, {%8,%9}, {%0,%1,%2,%3};" \
        : "+f"((d)[0]), "+f"((d)[1]), "+f"((d)[2]), "+f"((d)[3]) \
        : "r"((a)[0]), "r"((a)[1]), "r"((a)[2]), "r"((a)[3]), "r"(b0), "r"(b1))

#define CP_A16(dst, src) \
    asm volatile("cp.async.cg.shared.global [%0], [%1], 16;" \
        :: "r"(dst), "l"(__cvta_generic_to_global(src)) : "memory")
#define CP_COMMIT() asm volatile("cp.async.commit_group;" ::: "memory")
#define CP_WAIT(n)  asm volatile("cp.async.wait_group %0;" :: "n"(n) : "memory")

// proj stage layout (48KB per stage, two stages)
#define P_A_HI 0
#define P_A_LO 16384
#define P_B_HI 32768
#define P_B_LO 40960
#define STAGE_SZ 49152
#define PIPE_SMEM (2 * STAGE_SZ)

// persistent step kernel smem: U-resident 128KB + 2 A stages 64KB
#define S2_U_OFF 0
#define S2_A_OFF 131072
#define S2_SMEM  196608

// =====================================================================
// conv kernels: fp32 -> bf16 hi/lo split.
// =====================================================================
__global__ void conv_u_kernel(const float* __restrict__ U_f,
                              const float* __restrict__ U_b)
{
    const int c   = blockIdx.x;
    const int dir = blockIdx.y;
    const float* __restrict__ U = dir ? U_b : U_f;
    const int g = c >> 9, u = c & 511;
    const int np = 4 * u + g;                 // gate-permuted col
    for (int k = threadIdx.x; k < KDIM; k += blockDim.x) {
        float v = U[(size_t)k * G4 + c];
        __nv_bfloat16 hi = __float2bfloat16(v);
        g_Ubf[dir][0][np][k] = hi;
        g_Ubf[dir][1][np][k] = __float2bfloat16(v - __bfloat162float(hi));
    }
}

__global__ void conv_w_kernel(const float* __restrict__ W_f,
                              const float* __restrict__ W_b)
{
    const int c   = blockIdx.x;
    const int dir = blockIdx.y;
    const float* __restrict__ W = dir ? W_b : W_f;
    for (int k = threadIdx.x; k < KDIM; k += blockDim.x) {
        float v = W[(size_t)k * G4 + c];
        __nv_bfloat16 hi = __float2bfloat16(v);
        g_Wbf[dir][0][c][k] = hi;
        g_Wbf[dir][1][c][k] = __float2bfloat16(v - __bfloat162float(hi));
    }
}

__global__ void conv_e_kernel(const int* __restrict__ x,
                              const float* __restrict__ emb)
{
    const int row = blockIdx.x;               // n*TSEQ + t
    const float* src = emb + (size_t)x[row] * EMBED;
    for (int k = threadIdx.x; k < EMBED; k += blockDim.x) {
        float v = src[k];
        __nv_bfloat16 hi = __float2bfloat16(v);
        g_xE[0][row][k] = hi;
        g_xE[1][row][k] = __float2bfloat16(v - __bfloat162float(hi));
    }
}

// =====================================================================
// Kernel 1: input projection via mma.sync bf16x3 (unchanged; tensor=75%).
// =====================================================================
__global__ __launch_bounds__(256) void proj_mma_kernel(
    const float* __restrict__ b_f, const float* __restrict__ b_b)
{
    extern __shared__ char smem[];
    const uint32_t sb = smem_u32(smem);

    const int tid  = threadIdx.x;
    const int lane = tid & 31;
    const int wid  = tid >> 5;
    const int n    = blockIdx.x;
    const int c0   = blockIdx.y * 64;
    const int dir  = blockIdx.z;
    const float* __restrict__ bias = dir ? b_b : b_f;

    const int wm = (wid & 3) * 32;
    const int wn = (wid >> 2) * 32;

    float acc[2][2][2][4];
    #pragma unroll
    for (int i = 0; i < 2; i++)
        #pragma unroll
        for (int g = 0; g < 2; g++)
            #pragma unroll
            for (int j = 0; j < 2; j++)
                #pragma unroll
                for (int q = 0; q < 4; q++) acc[i][g][j][q] = 0.f;

    const int a_ro  = lane & 15;
    const int a_kb  = (lane >> 4) * 16;
    const int b_ro  = (lane & 7) + (lane >> 4) * 8;
    const int b_kb  = ((lane >> 3) & 1) * 16;

    const int ar = tid >> 3, acc16 = (tid & 7) * 16;
    const size_t arow0 = (size_t)n * TSEQ;

    #pragma unroll
    for (int s = 0; s < 2; s++) {
        #pragma unroll
        for (int it = 0; it < 4; it++) {
            int r = ar + it * 32;
            CP_A16(sb + (s ? P_A_LO : P_A_HI) + SWZ(r, acc16),
                   (const char*)&g_xE[s][arow0 + r][0] + acc16);
        }
        #pragma unroll
        for (int it = 0; it < 2; it++) {
            int r = ar + it * 32;
            CP_A16(sb + (s ? P_B_LO : P_B_HI) + SWZ(r, acc16),
                   (const char*)&g_Wbf[dir][s][c0 + r][0] + acc16);
        }
    }
    CP_COMMIT();

    for (int kc = 0; kc < NCHUNK; kc++) {
        if (kc + 1 < NCHUNK) {
            const int sbase = ((kc + 1) & 1) * STAGE_SZ;
            const int kb = (kc + 1) * KC;
            #pragma unroll
            for (int s = 0; s < 2; s++) {
                #pragma unroll
                for (int it = 0; it < 4; it++) {
                    int r = ar + it * 32;
                    CP_A16(sb + sbase + (s ? P_A_LO : P_A_HI) + SWZ(r, acc16),
                           (const char*)&g_xE[s][arow0 + r][kb] + acc16);
                }
                #pragma unroll
                for (int it = 0; it < 2; it++) {
                    int r = ar + it * 32;
                    CP_A16(sb + sbase + (s ? P_B_LO : P_B_HI) + SWZ(r, acc16),
                           (const char*)&g_Wbf[dir][s][c0 + r][kb] + acc16);
                }
            }
            CP_COMMIT();
            CP_WAIT(1);
        } else {
            CP_WAIT(0);
        }
        __syncthreads();

        const uint32_t stg = sb + (kc & 1) * STAGE_SZ;
        #pragma unroll
        for (int ks = 0; ks < 4; ks++) {
            uint32_t ah[2][4], al[2][4], bh[2][4], bl[2][4];
            #pragma unroll
            for (int i = 0; i < 2; i++) {
                LDSM_X4(ah[i][0], ah[i][1], ah[i][2], ah[i][3],
                        stg + P_A_HI + SWZ(wm + i * 16 + a_ro, ks * 32 + a_kb));
                LDSM_X4(al[i][0], al[i][1], al[i][2], al[i][3],
                        stg + P_A_LO + SWZ(wm + i * 16 + a_ro, ks * 32 + a_kb));
            }
            #pragma unroll
            for (int g = 0; g < 2; g++) {
                LDSM_X4(bh[g][0], bh[g][1], bh[g][2], bh[g][3],
                        stg + P_B_HI + SWZ(wn + g * 16 + b_ro, ks * 32 + b_kb));
                LDSM_X4(bl[g][0], bl[g][1], bl[g][2], bl[g][3],
                        stg + P_B_LO + SWZ(wn + g * 16 + b_ro, ks * 32 + b_kb));
            }
            #pragma unroll
            for (int i = 0; i < 2; i++)
                #pragma unroll
                for (int g = 0; g < 2; g++)
                    #pragma unroll
                    for (int j = 0; j < 2; j++) {
                        MMA16816(acc[i][g][j], ah[i], bh[g][2 * j], bh[g][2 * j + 1]);
                        MMA16816(acc[i][g][j], ah[i], bl[g][2 * j], bl[g][2 * j + 1]);
                        MMA16816(acc[i][g][j], al[i], bh[g][2 * j], bh[g][2 * j + 1]);
                    }
        }
        if (kc + 1 < NCHUNK) __syncthreads();
    }

    #pragma unroll
    for (int i = 0; i < 2; i++)
        #pragma unroll
        for (int g = 0; g < 2; g++)
            #pragma unroll
            for (int j = 0; j < 2; j++) {
                int col = c0 + wn + g * 16 + j * 8 + (lane & 3) * 2;
                float bi0 = bias[col], bi1 = bias[col + 1];
                int r0 = wm + i * 16 + (lane >> 2);
                int r1 = r0 + 8;
                int ts0 = dir ? (TSEQ - 1 - r0) : r0;
                int ts1 = dir ? (TSEQ - 1 - r1) : r1;
                *(float2*)&g_xW[dir][ts0][n][col] =
                    make_float2(acc[i][g][j][0] + bi0, acc[i][g][j][1] + bi1);
                *(float2*)&g_xW[dir][ts1][n][col] =
                    make_float2(acc[i][g][j][2] + bi0, acc[i][g][j][3] + bi1);
            }
}

// =====================================================================
// Kernel 2: PERSISTENT recurrence with dataflow flags (no per-step grid
// barrier). 128 co-resident CTAs; CTA = (dir, mtile, ntile) owning
// M=128 rows x 16 units. W flags gate RAW (h written -> consumed);
// R flags gate WAR (h consumed -> buffer overwritten).
// =====================================================================
__global__ __launch_bounds__(256) void persist_step_kernel(const int* __restrict__ x)
{
    extern __shared__ char smem[];
    const uint32_t sb = smem_u32(smem);

    const int tid  = threadIdx.x;
    const int lane = tid & 31;
    const int wid  = tid >> 5;
    const int bid  = blockIdx.x;
    const int dir   = bid >> 6;
    const int mtile = (bid >> 5) & 1;
    const int ntile = bid & 31;
    const int m0  = mtile * 128;
    const int np0 = ntile * 64;
    const int ub0 = ntile * 16;

    float* zs = (float*)(smem + S2_A_OFF);    // 128x64 fp32, overlays A stage 0

    // ---- reset my flags, then one grid barrier (replay determinism) ----
    if (tid == 0) {
        g_Wf[dir][mtile][ntile] = 0;
        g_Rf[dir][mtile][ntile] = 0;
        __threadfence();
        atomicAdd(&g_bar_cnt, 1u);
        while (*((volatile unsigned*)&g_bar_cnt) < (unsigned)NCTA) { }
        __threadfence();
    }
    __syncthreads();

    // ---- one-time: preload U slice (hi/lo, all 8 chunks) into smem ----
    #pragma unroll
    for (int it = 0; it < 32; it++) {
        int j = tid + it * 256;
        int split = j >> 12;
        int kc    = (j >> 9) & 7;
        int row   = (j >> 3) & 63;
        int g8    = (j & 7) * 16;
        CP_A16(sb + S2_U_OFF + split * 65536 + kc * 8192 + SWZ(row, g8),
               (const char*)&g_Ubf[dir][split][np0 + row][kc * KC] + g8);
    }
    CP_COMMIT();
    CP_WAIT(0);
    __syncthreads();

    const int wm = (wid & 3) * 32;
    const int wn = (wid >> 2) * 32;
    const int a_ro  = lane & 15;
    const int a_kb  = (lane >> 4) * 16;
    const int b_ro  = (lane & 7) + (lane >> 4) * 8;
    const int b_kb  = ((lane >> 3) & 1) * 16;
    // my cp.async column slice -> producer flag index within a chunk
    const int my_prod = (tid & 7) >> 1;

    for (int t = 0; t < TSEQ; t++) {
        const int pr = t & 1, pw = pr ^ 1;

        if (t > 0) {
            float acc[2][2][2][4];
            #pragma unroll
            for (int i = 0; i < 2; i++)
                #pragma unroll
                for (int g = 0; g < 2; g++)
                    #pragma unroll
                    for (int j = 0; j < 2; j++)
                        #pragma unroll
                        for (int q = 0; q < 4; q++) acc[i][g][j][q] = 0.f;

            // wait my producer for chunk 0, then issue chunk 0 A-stream
            while (ld_acq(&g_Wf[dir][mtile][my_prod]) < t) { }
            __threadfence();
            #pragma unroll
            for (int it = 0; it < 8; it++) {
                int j = tid + it * 256;
                int split = j >> 10;
                int r     = (j >> 3) & 127;
                int g8    = (j & 7) * 16;
                CP_A16(sb + S2_A_OFF + split * 16384 + SWZ(r, g8),
                       (const char*)&g_hbf[dir][pr][split][m0 + r][0] + g8);
            }
            CP_COMMIT();

            for (int kc = 0; kc < NCHUNK; kc++) {
                if (kc + 1 < NCHUNK) {
                    // wait my producer for chunk kc+1, then issue its A-stream
                    while (ld_acq(&g_Wf[dir][mtile][4 * (kc + 1) + my_prod]) < t) { }
                    __threadfence();
                    const int sbase = ((kc + 1) & 1) * 32768;
                    const int kb = (kc + 1) * KC;
                    #pragma unroll
                    for (int it = 0; it < 8; it++) {
                        int j = tid + it * 256;
                        int split = j >> 10;
                        int r     = (j >> 3) & 127;
                        int g8    = (j & 7) * 16;
                        CP_A16(sb + S2_A_OFF + sbase + split * 16384 + SWZ(r, g8),
                               (const char*)&g_hbf[dir][pr][split][m0 + r][kb] + g8);
                    }
                    CP_COMMIT();
                    CP_WAIT(1);
                } else {
                    CP_WAIT(0);
                }
                __syncthreads();
                if (kc == NCHUNK - 1 && tid == 0) {
                    // all A reads of step t complete -> publish R
                    __threadfence();
                    st_rel(&g_Rf[dir][mtile][ntile], t);
                }

                const uint32_t sa = sb + S2_A_OFF + (kc & 1) * 32768;
                const uint32_t su = sb + S2_U_OFF + kc * 8192;
                #pragma unroll
                for (int ks = 0; ks < 4; ks++) {
                    uint32_t ah[2][4], al[2][4], bh[2][4], bl[2][4];
                    #pragma unroll
                    for (int i = 0; i < 2; i++) {
                        LDSM_X4(ah[i][0], ah[i][1], ah[i][2], ah[i][3],
                                sa + SWZ(wm + i * 16 + a_ro, ks * 32 + a_kb));
                        LDSM_X4(al[i][0], al[i][1], al[i][2], al[i][3],
                                sa + 16384 + SWZ(wm + i * 16 + a_ro, ks * 32 + a_kb));
                    }
                    #pragma unroll
                    for (int g = 0; g < 2; g++) {
                        LDSM_X4(bh[g][0], bh[g][1], bh[g][2], bh[g][3],
                                su + SWZ(wn + g * 16 + b_ro, ks * 32 + b_kb));
                        LDSM_X4(bl[g][0], bl[g][1], bl[g][2], bl[g][3],
                                su + 65536 + SWZ(wn + g * 16 + b_ro, ks * 32 + b_kb));
                    }
                    #pragma unroll
                    for (int i = 0; i < 2; i++)
                        #pragma unroll
                        for (int g = 0; g < 2; g++)
                            #pragma unroll
                            for (int j = 0; j < 2; j++) {
                                MMA16816(acc[i][g][j], ah[i], bh[g][2 * j], bh[g][2 * j + 1]);
                                MMA16816(acc[i][g][j], ah[i], bl[g][2 * j], bl[g][2 * j + 1]);
                                MMA16816(acc[i][g][j], al[i], bh[g][2 * j], bh[g][2 * j + 1]);
                            }
                }
                if (kc + 1 < NCHUNK) __syncthreads();
            }

            // write z (128x64) to smem (overlays A stage 0; chunk7 used stage 1)
            #pragma unroll
            for (int i = 0; i < 2; i++)
                #pragma unroll
                for (int g = 0; g < 2; g++)
                    #pragma unroll
                    for (int j = 0; j < 2; j++) {
                        int r = wm + i * 16 + (lane >> 2);
                        int c = wn + g * 16 + j * 8 + (lane & 3) * 2;
                        *(float2*)&zs[r * 64 + c] =
                            make_float2(acc[i][g][j][0], acc[i][g][j][1]);
                        *(float2*)&zs[(r + 8) * 64 + c] =
                            make_float2(acc[i][g][j][2], acc[i][g][j][3]);
                    }
            __syncthreads();
        } else {
            #pragma unroll
            for (int i = 0; i < 32; i++) zs[tid + i * 256] = 0.f;
            __syncthreads();
        }

        // ---- WAR guard: step-(t-1) readers of buffer pw must be done ----
        if (wid == 0) {
            while (ld_acq(&g_Rf[dir][mtile][lane]) < t - 1) { }
        }
        __syncthreads();

        // ---- gate epilogue: 128 rows x 16 units, 8 items/thread ----
        const float* xw = &g_xW[dir][t][0][0];
        const int tt = dir ? (TSEQ - 1 - t) : t;
        #pragma unroll
        for (int i = 0; i < 8; i++) {
            int idx = tid + i * 256;
            int r = idx >> 4, ul = idx & 15;
            int gr = m0 + r, gu = ub0 + ul;
            const float* xwr = xw + (size_t)gr * G4;
            float4 z4 = *(const float4*)&zs[r * 64 + ul * 4];
            float zi = z4.x + xwr[gu];
            float zf = z4.y + xwr[512 + gu];
            float zg = z4.z + xwr[1024 + gu];
            float zo = z4.w + xwr[1536 + gu];
            float ig = 1.f / (1.f + expf(-zi));
            float fg = 1.f / (1.f + expf(-zf));
            float gg = tanhf(zg);
            float og = 1.f / (1.f + expf(-zo));
            float cold = (t > 0) ? g_c[dir][pr][gr][gu] : 0.f;
            float cn = fg * cold + ig * gg;
            float hn = og * tanhf(cn);
            bool msk = x[gr * TSEQ + tt] != 0;

            __nv_bfloat16 oh = __float2bfloat16(0.f), ol = oh;
            if (t > 0) { oh = g_hbf[dir][pr][0][gr][gu]; ol = g_hbf[dir][pr][1][gr][gu]; }
            __nv_bfloat16 nh, nl;
            if (msk) {
                nh = __float2bfloat16(hn);
                nl = __float2bfloat16(hn - __bfloat162float(nh));
            } else { nh = oh; nl = ol; }
            g_c[dir][pw][gr][gu] = msk ? cn : cold;
            g_hbf[dir][pw][0][gr][gu] = nh;
            g_hbf[dir][pw][1][gr][gu] = nl;
        }

        // ---- publish W: my epilogue for step t is done ----
        __syncthreads();
        if (tid == 0) {
            __threadfence();
            st_rel(&g_Wf[dir][mtile][ntile], t + 1);
        }
    }

    // ---- exit round: reset barrier counter for next graph replay ----
    if (tid == 0) {
        atomicAdd(&g_bar_cnt, 1u);
        if (bid == 0) {
            while (*((volatile unsigned*)&g_bar_cnt) < 2u * (unsigned)NCTA) { }
            g_bar_cnt = 0;
            __threadfence();
        }
    }
}

// =====================================================================
// Kernel 3: concat [h_fwd, h_bwd] -> out fp32 (final state in buf 0).
// =====================================================================
__global__ void copy_out_kernel(float* __restrict__ out)
{
    int i = blockIdx.x * 256 + threadIdx.x;
    int n   = i >> 10;
    int u   = i & 1023;
    int dir = u >> 9;
    int uu  = u & 511;
    out[i] = __bfloat162float(g_hbf[dir][0][0][n][uu]) +
             __bfloat162float(g_hbf[dir][0][1][n][uu]);
}

// =====================================================================
extern "C" void kernel_launch(void* const* d_in, const int* in_sizes, int n_in,
                              void* d_out, int out_size)
{
    (void)in_sizes; (void)n_in; (void)out_size;
    const int*   x    = (const int*)  d_in[0];
    const float* emb  = (const float*)d_in[1];
    const float* W_f  = (const float*)d_in[2];
    const float* U_f  = (const float*)d_in[3];
    const float* b_f  = (const float*)d_in[4];
    const float* W_b  = (const float*)d_in[5];
    const float* U_b  = (const float*)d_in[6];
    const float* b_b  = (const float*)d_in[7];
    float* out = (float*)d_out;

    cudaFuncSetAttribute(proj_mma_kernel,
        cudaFuncAttributeMaxDynamicSharedMemorySize, PIPE_SMEM);
    cudaFuncSetAttribute(persist_step_kernel,
        cudaFuncAttributeMaxDynamicSharedMemorySize, S2_SMEM);

    conv_u_kernel<<<dim3(G4, 2), 128>>>(U_f, U_b);
    conv_w_kernel<<<dim3(G4, 2), 128>>>(W_f, W_b);
    conv_e_kernel<<<NSEQ * TSEQ, 256>>>(x, emb);

    dim3 pgrid(NSEQ, G4 / 64, 2);              // (256, 32, 2)
    proj_mma_kernel<<<pgrid, 256, PIPE_SMEM>>>(b_f, b_b);

    persist_step_kernel<<<NCTA, 256, S2_SMEM>>>(x);

    copy_out_kernel<<<(NSEQ * 1024) / 256, 256>>>(out);
}

// round 15
// speedup vs baseline: 1.6029x; 1.6029x over previous
#include <cuda_runtime.h>
#include <cuda_bf16.h>
#include <math.h>
#include <stdint.h>

#define NSEQ  256     // B*S
#define TSEQ  128
#define EMBED 512
#define UNITS 512
#define G4    2048    // 4*UNITS
#define KDIM  512
#define KC    64      // k-chunk (bf16 elems) = 128B row
#define NCHUNK 8
#define NCTA  128     // persistent grid size

// ---------------- scratch (__device__ globals, allocation-free) ----------------
__device__ __align__(16) float g_xW[2][TSEQ][NSEQ][G4];               // 512 MB
__device__ __align__(16) __nv_bfloat16 g_hbf[2][2][2][NSEQ][UNITS];   // h hi/lo, dbl-buf
__device__ __align__(16) __nv_bfloat16 g_Ubf[2][2][G4][KDIM];         // U hi/lo, permuted
__device__ __align__(16) __nv_bfloat16 g_Wbf[2][2][G4][KDIM];         // W hi/lo, natural
__device__ __align__(16) __nv_bfloat16 g_xE[2][NSEQ * TSEQ][EMBED];   // emb hi/lo, 64 MB
__device__ __align__(16) float g_c[2][2][NSEQ][UNITS];
__device__ unsigned g_bar_cnt;                                        // grid barrier

// ---------------- helpers ----------------
__device__ __forceinline__ uint32_t smem_u32(const void* p) {
    uint32_t a;
    asm("{ .reg .u64 t; cvta.to.shared.u64 t, %1; cvt.u32.u64 %0, t; }" : "=r"(a) : "l"(p));
    return a;
}
#define SWZ(r, kb) (((r) * 128) + ((kb) ^ (((r) & 7) << 4)))

#define LDSM_X4(r0, r1, r2, r3, addr) \
    asm volatile("ldmatrix.sync.aligned.m8n8.x4.shared.b16 {%0,%1,%2,%3}, [%4];" \
        : "=r"(r0), "=r"(r1), "=r"(r2), "=r"(r3) : "r"(addr))

#define MMA16816(d, a, b0, b1) \
    asm volatile("mma.sync.aligned.m16n8k16.row.col.f32.bf16.bf16.f32 " \
        "{%0,%1,%2,%3}, {%4,%5,%6,%7}, {%8,%9}, {%0,%1,%2,%3};" \
        : "+f"((d)[0]), "+f"((d)[1]), "+f"((d)[2]), "+f"((d)[3]) \
        : "r"((a)[0]), "r"((a)[1]), "r"((a)[2]), "r"((a)[3]), "r"(b0), "r"(b1))

#define CP_A16(dst, src) \
    asm volatile("cp.async.cg.shared.global [%0], [%1], 16;" \
        :: "r"(dst), "l"(__cvta_generic_to_global(src)) : "memory")
#define CP_COMMIT() asm volatile("cp.async.commit_group;" ::: "memory")
#define CP_WAIT(n)  asm volatile("cp.async.wait_group %0;" :: "n"(n) : "memory")

// proj stage layout (48KB per stage, two stages)
#define P_A_HI 0
#define P_A_LO 16384
#define P_B_HI 32768
#define P_B_LO 40960
#define STAGE_SZ 49152
#define PIPE_SMEM (2 * STAGE_SZ)

// persistent step kernel smem:
//   U-resident 128KB + 2 A stages 64KB + xW prefetch 32KB = 224KB
#define S2_U_OFF 0
#define S2_A_OFF 131072
#define S2_PF_OFF 196608
#define S2_SMEM  229376

// =====================================================================
// conv kernels: fp32 -> bf16 hi/lo split.
// =====================================================================
__global__ void conv_u_kernel(const float* __restrict__ U_f,
                              const float* __restrict__ U_b)
{
    const int c   = blockIdx.x;
    const int dir = blockIdx.y;
    const float* __restrict__ U = dir ? U_b : U_f;
    const int g = c >> 9, u = c & 511;
    const int np = 4 * u + g;                 // gate-permuted col
    for (int k = threadIdx.x; k < KDIM; k += blockDim.x) {
        float v = U[(size_t)k * G4 + c];
        __nv_bfloat16 hi = __float2bfloat16(v);
        g_Ubf[dir][0][np][k] = hi;
        g_Ubf[dir][1][np][k] = __float2bfloat16(v - __bfloat162float(hi));
    }
}

__global__ void conv_w_kernel(const float* __restrict__ W_f,
                              const float* __restrict__ W_b)
{
    const int c   = blockIdx.x;
    const int dir = blockIdx.y;
    const float* __restrict__ W = dir ? W_b : W_f;
    for (int k = threadIdx.x; k < KDIM; k += blockDim.x) {
        float v = W[(size_t)k * G4 + c];
        __nv_bfloat16 hi = __float2bfloat16(v);
        g_Wbf[dir][0][c][k] = hi;
        g_Wbf[dir][1][c][k] = __float2bfloat16(v - __bfloat162float(hi));
    }
}

__global__ void conv_e_kernel(const int* __restrict__ x,
                              const float* __restrict__ emb)
{
    const int row = blockIdx.x;               // n*TSEQ + t
    const float* src = emb + (size_t)x[row] * EMBED;
    for (int k = threadIdx.x; k < EMBED; k += blockDim.x) {
        float v = src[k];
        __nv_bfloat16 hi = __float2bfloat16(v);
        g_xE[0][row][k] = hi;
        g_xE[1][row][k] = __float2bfloat16(v - __bfloat162float(hi));
    }
}

// =====================================================================
// Kernel 1: input projection via mma.sync bf16x3 (unchanged; tensor=75%).
// =====================================================================
__global__ __launch_bounds__(256) void proj_mma_kernel(
    const float* __restrict__ b_f, const float* __restrict__ b_b)
{
    extern __shared__ char smem[];
    const uint32_t sb = smem_u32(smem);

    const int tid  = threadIdx.x;
    const int lane = tid & 31;
    const int wid  = tid >> 5;
    const int n    = blockIdx.x;
    const int c0   = blockIdx.y * 64;
    const int dir  = blockIdx.z;
    const float* __restrict__ bias = dir ? b_b : b_f;

    const int wm = (wid & 3) * 32;
    const int wn = (wid >> 2) * 32;

    float acc[2][2][2][4];
    #pragma unroll
    for (int i = 0; i < 2; i++)
        #pragma unroll
        for (int g = 0; g < 2; g++)
            #pragma unroll
            for (int j = 0; j < 2; j++)
                #pragma unroll
                for (int q = 0; q < 4; q++) acc[i][g][j][q] = 0.f;

    const int a_ro  = lane & 15;
    const int a_kb  = (lane >> 4) * 16;
    const int b_ro  = (lane & 7) + (lane >> 4) * 8;
    const int b_kb  = ((lane >> 3) & 1) * 16;

    const int ar = tid >> 3, acc16 = (tid & 7) * 16;
    const size_t arow0 = (size_t)n * TSEQ;

    #pragma unroll
    for (int s = 0; s < 2; s++) {
        #pragma unroll
        for (int it = 0; it < 4; it++) {
            int r = ar + it * 32;
            CP_A16(sb + (s ? P_A_LO : P_A_HI) + SWZ(r, acc16),
                   (const char*)&g_xE[s][arow0 + r][0] + acc16);
        }
        #pragma unroll
        for (int it = 0; it < 2; it++) {
            int r = ar + it * 32;
            CP_A16(sb + (s ? P_B_LO : P_B_HI) + SWZ(r, acc16),
                   (const char*)&g_Wbf[dir][s][c0 + r][0] + acc16);
        }
    }
    CP_COMMIT();

    for (int kc = 0; kc < NCHUNK; kc++) {
        if (kc + 1 < NCHUNK) {
            const int sbase = ((kc + 1) & 1) * STAGE_SZ;
            const int kb = (kc + 1) * KC;
            #pragma unroll
            for (int s = 0; s < 2; s++) {
                #pragma unroll
                for (int it = 0; it < 4; it++) {
                    int r = ar + it * 32;
                    CP_A16(sb + sbase + (s ? P_A_LO : P_A_HI) + SWZ(r, acc16),
                           (const char*)&g_xE[s][arow0 + r][kb] + acc16);
                }
                #pragma unroll
                for (int it = 0; it < 2; it++) {
                    int r = ar + it * 32;
                    CP_A16(sb + sbase + (s ? P_B_LO : P_B_HI) + SWZ(r, acc16),
                           (const char*)&g_Wbf[dir][s][c0 + r][kb] + acc16);
                }
            }
            CP_COMMIT();
            CP_WAIT(1);
        } else {
            CP_WAIT(0);
        }
        __syncthreads();

        const uint32_t stg = sb + (kc & 1) * STAGE_SZ;
        #pragma unroll
        for (int ks = 0; ks < 4; ks++) {
            uint32_t ah[2][4], al[2][4], bh[2][4], bl[2][4];
            #pragma unroll
            for (int i = 0; i < 2; i++) {
                LDSM_X4(ah[i][0], ah[i][1], ah[i][2], ah[i][3],
                        stg + P_A_HI + SWZ(wm + i * 16 + a_ro, ks * 32 + a_kb));
                LDSM_X4(al[i][0], al[i][1], al[i][2], al[i][3],
                        stg + P_A_LO + SWZ(wm + i * 16 + a_ro, ks * 32 + a_kb));
            }
            #pragma unroll
            for (int g = 0; g < 2; g++) {
                LDSM_X4(bh[g][0], bh[g][1], bh[g][2], bh[g][3],
                        stg + P_B_HI + SWZ(wn + g * 16 + b_ro, ks * 32 + b_kb));
                LDSM_X4(bl[g][0], bl[g][1], bl[g][2], bl[g][3],
                        stg + P_B_LO + SWZ(wn + g * 16 + b_ro, ks * 32 + b_kb));
            }
            #pragma unroll
            for (int i = 0; i < 2; i++)
                #pragma unroll
                for (int g = 0; g < 2; g++)
                    #pragma unroll
                    for (int j = 0; j < 2; j++) {
                        MMA16816(acc[i][g][j], ah[i], bh[g][2 * j], bh[g][2 * j + 1]);
                        MMA16816(acc[i][g][j], ah[i], bl[g][2 * j], bl[g][2 * j + 1]);
                        MMA16816(acc[i][g][j], al[i], bh[g][2 * j], bh[g][2 * j + 1]);
                    }
        }
        if (kc + 1 < NCHUNK) __syncthreads();
    }

    #pragma unroll
    for (int i = 0; i < 2; i++)
        #pragma unroll
        for (int g = 0; g < 2; g++)
            #pragma unroll
            for (int j = 0; j < 2; j++) {
                int col = c0 + wn + g * 16 + j * 8 + (lane & 3) * 2;
                float bi0 = bias[col], bi1 = bias[col + 1];
                int r0 = wm + i * 16 + (lane >> 2);
                int r1 = r0 + 8;
                int ts0 = dir ? (TSEQ - 1 - r0) : r0;
                int ts1 = dir ? (TSEQ - 1 - r1) : r1;
                *(float2*)&g_xW[dir][ts0][n][col] =
                    make_float2(acc[i][g][j][0] + bi0, acc[i][g][j][1] + bi1);
                *(float2*)&g_xW[dir][ts1][n][col] =
                    make_float2(acc[i][g][j][2] + bi0, acc[i][g][j][3] + bi1);
            }
}

// =====================================================================
// Kernel 2: PERSISTENT recurrence (R11 structure: per-step grid barrier)
// + NEW: xW tile prefetched into smem via cp.async at step start,
// overlapping the whole GEMM phase; epilogue reads smem, not DRAM.
// =====================================================================
__global__ __launch_bounds__(256) void persist_step_kernel(const int* __restrict__ x)
{
    extern __shared__ char smem[];
    const uint32_t sb = smem_u32(smem);

    const int tid  = threadIdx.x;
    const int lane = tid & 31;
    const int wid  = tid >> 5;
    const int bid  = blockIdx.x;
    const int dir   = bid >> 6;
    const int mtile = (bid >> 5) & 1;
    const int ntile = bid & 31;
    const int m0  = mtile * 128;
    const int np0 = ntile * 64;
    const int ub0 = ntile * 16;

    float* zs = (float*)(smem + S2_A_OFF);          // 128x64 fp32, overlays A stage 0
    const float* xs = (const float*)(smem + S2_PF_OFF);  // xW tile [r][gate][16]

    // ---- one-time: preload U slice (hi/lo, all 8 chunks) into smem ----
    #pragma unroll
    for (int it = 0; it < 32; it++) {
        int j = tid + it * 256;
        int split = j >> 12;
        int kc    = (j >> 9) & 7;
        int row   = (j >> 3) & 63;
        int g8    = (j & 7) * 16;
        CP_A16(sb + S2_U_OFF + split * 65536 + kc * 8192 + SWZ(row, g8),
               (const char*)&g_Ubf[dir][split][np0 + row][kc * KC] + g8);
    }
    CP_COMMIT();
    CP_WAIT(0);
    __syncthreads();

    const int wm = (wid & 3) * 32;
    const int wn = (wid >> 2) * 32;
    const int a_ro  = lane & 15;
    const int a_kb  = (lane >> 4) * 16;
    const int b_ro  = (lane & 7) + (lane >> 4) * 8;
    const int b_kb  = ((lane >> 3) & 1) * 16;
    const int ar = tid >> 3, acc16 = (tid & 7) * 16;
    // xW prefetch coords: 2048 granules, 8/thread
    const int pf_r = tid >> 4, pf_seg = tid & 15;
    const int pf_gate = pf_seg >> 2, pf_q = pf_seg & 3;

    for (int t = 0; t < TSEQ; t++) {
        const int pr = t & 1, pw = pr ^ 1;

        if (t > 0) {
            float acc[2][2][2][4];
            #pragma unroll
            for (int i = 0; i < 2; i++)
                #pragma unroll
                for (int g = 0; g < 2; g++)
                    #pragma unroll
                    for (int j = 0; j < 2; j++)
                        #pragma unroll
                        for (int q = 0; q < 4; q++) acc[i][g][j][q] = 0.f;

            // ---- issue xW prefetch (no deps; retires during GEMM) ----
            #pragma unroll
            for (int it = 0; it < 8; it++) {
                int r = pf_r + it * 16;
                CP_A16(sb + S2_PF_OFF + r * 256 + pf_gate * 64 + pf_q * 16,
                       (const char*)&g_xW[dir][t][m0 + r][pf_gate * 512 + ub0] + pf_q * 16);
            }
            CP_COMMIT();

            // ---- issue A chunk 0 ----
            #pragma unroll
            for (int it = 0; it < 8; it++) {
                int j = tid + it * 256;
                int split = j >> 10;
                int r     = (j >> 3) & 127;
                int g8    = (j & 7) * 16;
                CP_A16(sb + S2_A_OFF + split * 16384 + SWZ(r, g8),
                       (const char*)&g_hbf[dir][pr][split][m0 + r][0] + g8);
            }
            CP_COMMIT();

            for (int kc = 0; kc < NCHUNK; kc++) {
                if (kc + 1 < NCHUNK) {
                    const int sbase = ((kc + 1) & 1) * 32768;
                    const int kb = (kc + 1) * KC;
                    #pragma unroll
                    for (int it = 0; it < 8; it++) {
                        int j = tid + it * 256;
                        int split = j >> 10;
                        int r     = (j >> 3) & 127;
                        int g8    = (j & 7) * 16;
                        CP_A16(sb + S2_A_OFF + sbase + split * 16384 + SWZ(r, g8),
                               (const char*)&g_hbf[dir][pr][split][m0 + r][kb] + g8);
                    }
                    CP_COMMIT();
                    CP_WAIT(1);
                } else {
                    CP_WAIT(0);
                }
                __syncthreads();

                const uint32_t sa = sb + S2_A_OFF + (kc & 1) * 32768;
                const uint32_t su = sb + S2_U_OFF + kc * 8192;
                #pragma unroll
                for (int ks = 0; ks < 4; ks++) {
                    uint32_t ah[2][4], al[2][4], bh[2][4], bl[2][4];
                    #pragma unroll
                    for (int i = 0; i < 2; i++) {
                        LDSM_X4(ah[i][0], ah[i][1], ah[i][2], ah[i][3],
                                sa + SWZ(wm + i * 16 + a_ro, ks * 32 + a_kb));
                        LDSM_X4(al[i][0], al[i][1], al[i][2], al[i][3],
                                sa + 16384 + SWZ(wm + i * 16 + a_ro, ks * 32 + a_kb));
                    }
                    #pragma unroll
                    for (int g = 0; g < 2; g++) {
                        LDSM_X4(bh[g][0], bh[g][1], bh[g][2], bh[g][3],
                                su + SWZ(wn + g * 16 + b_ro, ks * 32 + b_kb));
                        LDSM_X4(bl[g][0], bl[g][1], bl[g][2], bl[g][3],
                                su + 65536 + SWZ(wn + g * 16 + b_ro, ks * 32 + b_kb));
                    }
                    #pragma unroll
                    for (int i = 0; i < 2; i++)
                        #pragma unroll
                        for (int g = 0; g < 2; g++)
                            #pragma unroll
                            for (int j = 0; j < 2; j++) {
                                MMA16816(acc[i][g][j], ah[i], bh[g][2 * j], bh[g][2 * j + 1]);
                                MMA16816(acc[i][g][j], ah[i], bl[g][2 * j], bl[g][2 * j + 1]);
                                MMA16816(acc[i][g][j], al[i], bh[g][2 * j], bh[g][2 * j + 1]);
                            }
                }
                if (kc + 1 < NCHUNK) __syncthreads();
            }

            // write z (128x64) to smem (overlays A stage 0; chunk7 used stage 1)
            #pragma unroll
            for (int i = 0; i < 2; i++)
                #pragma unroll
                for (int g = 0; g < 2; g++)
                    #pragma unroll
                    for (int j = 0; j < 2; j++) {
                        int r = wm + i * 16 + (lane >> 2);
                        int c = wn + g * 16 + j * 8 + (lane & 3) * 2;
                        *(float2*)&zs[r * 64 + c] =
                            make_float2(acc[i][g][j][0], acc[i][g][j][1]);
                        *(float2*)&zs[(r + 8) * 64 + c] =
                            make_float2(acc[i][g][j][2], acc[i][g][j][3]);
                    }
            __syncthreads();
        } else {
            // t == 0: prefetch xW, zero z
            #pragma unroll
            for (int it = 0; it < 8; it++) {
                int r = pf_r + it * 16;
                CP_A16(sb + S2_PF_OFF + r * 256 + pf_gate * 64 + pf_q * 16,
                       (const char*)&g_xW[dir][0][m0 + r][pf_gate * 512 + ub0] + pf_q * 16);
            }
            CP_COMMIT();
            #pragma unroll
            for (int i = 0; i < 32; i++) zs[tid + i * 256] = 0.f;
            CP_WAIT(0);
            __syncthreads();
        }

        // ---- gate epilogue: 128 rows x 16 units, 8 items/thread ----
        const int tt = dir ? (TSEQ - 1 - t) : t;
        #pragma unroll
        for (int i = 0; i < 8; i++) {
            int idx = tid + i * 256;
            int r = idx >> 4, ul = idx & 15;
            int gr = m0 + r, gu = ub0 + ul;
            float4 z4 = *(const float4*)&zs[r * 64 + ul * 4];
            float zi = z4.x + xs[r * 64 + ul];
            float zf = z4.y + xs[r * 64 + 16 + ul];
            float zg = z4.z + xs[r * 64 + 32 + ul];
            float zo = z4.w + xs[r * 64 + 48 + ul];
            float ig = 1.f / (1.f + expf(-zi));
            float fg = 1.f / (1.f + expf(-zf));
            float gg = tanhf(zg);
            float og = 1.f / (1.f + expf(-zo));
            float cold = (t > 0) ? g_c[dir][pr][gr][gu] : 0.f;
            float cn = fg * cold + ig * gg;
            float hn = og * tanhf(cn);
            bool msk = x[gr * TSEQ + tt] != 0;

            __nv_bfloat16 oh = __float2bfloat16(0.f), ol = oh;
            if (t > 0) { oh = g_hbf[dir][pr][0][gr][gu]; ol = g_hbf[dir][pr][1][gr][gu]; }
            __nv_bfloat16 nh, nl;
            if (msk) {
                nh = __float2bfloat16(hn);
                nl = __float2bfloat16(hn - __bfloat162float(nh));
            } else { nh = oh; nl = ol; }
            g_c[dir][pw][gr][gu] = msk ? cn : cold;
            g_hbf[dir][pw][0][gr][gu] = nh;
            g_hbf[dir][pw][1][gr][gu] = nl;
        }

        // ---- grid barrier: all CTAs finish step t before step t+1 ----
        __syncthreads();
        if (tid == 0) {
            __threadfence();
            atomicAdd(&g_bar_cnt, 1u);
            const unsigned target = (unsigned)NCTA * (unsigned)(t + 1);
            while (*((volatile unsigned*)&g_bar_cnt) < target) { }
            __threadfence();
        }
        __syncthreads();
    }

    // ---- exit round: reset counter for the next graph replay ----
    if (tid == 0) {
        atomicAdd(&g_bar_cnt, 1u);
        if (bid == 0) {
            const unsigned target = (unsigned)NCTA * (unsigned)TSEQ + (unsigned)NCTA;
            while (*((volatile unsigned*)&g_bar_cnt) < target) { }
            g_bar_cnt = 0;
            __threadfence();
        }
    }
}

// =====================================================================
// Kernel 3: concat [h_fwd, h_bwd] -> out fp32 (final state in buf 0).
// =====================================================================
__global__ void copy_out_kernel(float* __restrict__ out)
{
    int i = blockIdx.x * 256 + threadIdx.x;
    int n   = i >> 10;
    int u   = i & 1023;
    int dir = u >> 9;
    int uu  = u & 511;
    out[i] = __bfloat162float(g_hbf[dir][0][0][n][uu]) +
             __bfloat162float(g_hbf[dir][0][1][n][uu]);
}

// =====================================================================
extern "C" void kernel_launch(void* const* d_in, const int* in_sizes, int n_in,
                              void* d_out, int out_size)
{
    (void)in_sizes; (void)n_in; (void)out_size;
    const int*   x    = (const int*)  d_in[0];
    const float* emb  = (const float*)d_in[1];
    const float* W_f  = (const float*)d_in[2];
    const float* U_f  = (const float*)d_in[3];
    const float* b_f  = (const float*)d_in[4];
    const float* W_b  = (const float*)d_in[5];
    const float* U_b  = (const float*)d_in[6];
    const float* b_b  = (const float*)d_in[7];
    float* out = (float*)d_out;

    cudaFuncSetAttribute(proj_mma_kernel,
        cudaFuncAttributeMaxDynamicSharedMemorySize, PIPE_SMEM);
    cudaFuncSetAttribute(persist_step_kernel,
        cudaFuncAttributeMaxDynamicSharedMemorySize, S2_SMEM);

    conv_u_kernel<<<dim3(G4, 2), 128>>>(U_f, U_b);
    conv_w_kernel<<<dim3(G4, 2), 128>>>(W_f, W_b);
    conv_e_kernel<<<NSEQ * TSEQ, 256>>>(x, emb);

    dim3 pgrid(NSEQ, G4 / 64, 2);              // (256, 32, 2)
    proj_mma_kernel<<<pgrid, 256, PIPE_SMEM>>>(b_f, b_b);

    persist_step_kernel<<<NCTA, 256, S2_SMEM>>>(x);

    copy_out_kernel<<<(NSEQ * 1024) / 256, 256>>>(out);
}

// round 16
// speedup vs baseline: 1.6132x; 1.0064x over previous
#include <cuda_runtime.h>
#include <cuda_bf16.h>
#include <math.h>
#include <stdint.h>

#define NSEQ  256     // B*S
#define TSEQ  128
#define EMBED 512
#define UNITS 512
#define G4    2048    // 4*UNITS
#define KDIM  512
#define KC    64      // k-chunk (bf16 elems) = 128B row
#define NCHUNK 8
#define NCTA  128     // persistent grid size

// ---------------- scratch (__device__ globals, allocation-free) ----------------
__device__ __align__(16) float g_xW[2][TSEQ][NSEQ][G4];               // 512 MB
__device__ __align__(16) __nv_bfloat16 g_hbf[2][2][2][NSEQ][UNITS];   // h hi/lo, dbl-buf
__device__ __align__(16) __nv_bfloat16 g_Ubf[2][2][G4][KDIM];         // U hi/lo, permuted
__device__ __align__(16) __nv_bfloat16 g_Wbf[2][2][G4][KDIM];         // W hi/lo, natural
__device__ __align__(16) __nv_bfloat16 g_xE[2][NSEQ * TSEQ][EMBED];   // emb hi/lo, 64 MB
__device__ __align__(16) float g_c[2][2][NSEQ][UNITS];
__device__ unsigned g_bar_cnt;                                        // grid barrier

// ---------------- helpers ----------------
__device__ __forceinline__ uint32_t smem_u32(const void* p) {
    uint32_t a;
    asm("{ .reg .u64 t; cvta.to.shared.u64 t, %1; cvt.u32.u64 %0, t; }" : "=r"(a) : "l"(p));
    return a;
}
// fast gates: __expf is EX2-based (rel err ~2^-21 in range), saturates cleanly
__device__ __forceinline__ float fsig(float x)  { return 1.f / (1.f + __expf(-x)); }
__device__ __forceinline__ float ftanh(float x) { return 2.f / (1.f + __expf(-2.f * x)) - 1.f; }

#define SWZ(r, kb) (((r) * 128) + ((kb) ^ (((r) & 7) << 4)))

#define LDSM_X4(r0, r1, r2, r3, addr) \
    asm volatile("ldmatrix.sync.aligned.m8n8.x4.shared.b16 {%0,%1,%2,%3}, [%4];" \
        : "=r"(r0), "=r"(r1), "=r"(r2), "=r"(r3) : "r"(addr))

#define MMA16816(d, a, b0, b1) \
    asm volatile("mma.sync.aligned.m16n8k16.row.col.f32.bf16.bf16.f32 " \
        "{%0,%1,%2,%3}, {%4,%5,%6,%7}, {%8,%9}, {%0,%1,%2,%3};" \
        : "+f"((d)[0]), "+f"((d)[1]), "+f"((d)[2]), "+f"((d)[3]) \
        : "r"((a)[0]), "r"((a)[1]), "r"((a)[2]), "r"((a)[3]), "r"(b0), "r"(b1))

#define CP_A16(dst, src) \
    asm volatile("cp.async.cg.shared.global [%0], [%1], 16;" \
        :: "r"(dst), "l"(__cvta_generic_to_global(src)) : "memory")
#define CP_COMMIT() asm volatile("cp.async.commit_group;" ::: "memory")
#define CP_WAIT(n)  asm volatile("cp.async.wait_group %0;" :: "n"(n) : "memory")

// proj stage layout (48KB per stage, two stages)
#define P_A_HI 0
#define P_A_LO 16384
#define P_B_HI 32768
#define P_B_LO 40960
#define STAGE_SZ 49152
#define PIPE_SMEM (2 * STAGE_SZ)

// persistent step kernel smem:
//   U-resident 128KB + 2 A stages 64KB + xW prefetch 32KB = 224KB
#define S2_U_OFF 0
#define S2_A_OFF 131072
#define S2_PF_OFF 196608
#define S2_SMEM  229376

// =====================================================================
// conv_uw: fp32 U/W -> bf16 hi/lo via 32x32 smem transpose.
// Coalesced loads over c; coalesced hi/lo writes over k.
// z = dir + 2*isU. U gets gate-permuted cols (np = 4u+g); W natural.
// =====================================================================
__global__ __launch_bounds__(256) void conv_uw_kernel(
    const float* __restrict__ U_f, const float* __restrict__ U_b,
    const float* __restrict__ W_f, const float* __restrict__ W_b)
{
    __shared__ float tile[32][33];
    const int c0  = blockIdx.x * 32;
    const int k0  = blockIdx.y * 32;
    const int z   = blockIdx.z;
    const int dir = z & 1, isU = z >> 1;
    const float* __restrict__ S = isU ? (dir ? U_b : U_f) : (dir ? W_b : W_f);
    const int tid = threadIdx.x;
    const int lc = tid & 31, lk = tid >> 5;

    #pragma unroll
    for (int i = 0; i < 4; i++) {
        int k = lk + i * 8;
        tile[k][lc] = S[(size_t)(k0 + k) * G4 + c0 + lc];
    }
    __syncthreads();

    const int cl = tid >> 3;
    const int kl = (tid & 7) * 4;
    const int c  = c0 + cl;
    const int np = isU ? (4 * (c & 511) + (c >> 9)) : c;
    __nv_bfloat16* dhi = isU ? &g_Ubf[dir][0][np][k0 + kl] : &g_Wbf[dir][0][np][k0 + kl];
    __nv_bfloat16* dlo = isU ? &g_Ubf[dir][1][np][k0 + kl] : &g_Wbf[dir][1][np][k0 + kl];

    __nv_bfloat16 h4[4], l4[4];
    #pragma unroll
    for (int j = 0; j < 4; j++) {
        float v = tile[kl + j][cl];
        __nv_bfloat16 hi = __float2bfloat16(v);
        h4[j] = hi;
        l4[j] = __float2bfloat16(v - __bfloat162float(hi));
    }
    *(uint2*)dhi = *(uint2*)h4;
    *(uint2*)dlo = *(uint2*)l4;
}

// gathered embeddings -> bf16 hi/lo (dir-independent; already coalesced)
__global__ void conv_e_kernel(const int* __restrict__ x,
                              const float* __restrict__ emb)
{
    const int row = blockIdx.x;               // n*TSEQ + t
    const float* src = emb + (size_t)x[row] * EMBED;
    for (int k = threadIdx.x; k < EMBED; k += blockDim.x) {
        float v = src[k];
        __nv_bfloat16 hi = __float2bfloat16(v);
        g_xE[0][row][k] = hi;
        g_xE[1][row][k] = __float2bfloat16(v - __bfloat162float(hi));
    }
}

// =====================================================================
// Kernel 1: input projection via mma.sync bf16x3 (unchanged; tensor=75%).
// =====================================================================
__global__ __launch_bounds__(256) void proj_mma_kernel(
    const float* __restrict__ b_f, const float* __restrict__ b_b)
{
    extern __shared__ char smem[];
    const uint32_t sb = smem_u32(smem);

    const int tid  = threadIdx.x;
    const int lane = tid & 31;
    const int wid  = tid >> 5;
    const int n    = blockIdx.x;
    const int c0   = blockIdx.y * 64;
    const int dir  = blockIdx.z;
    const float* __restrict__ bias = dir ? b_b : b_f;

    const int wm = (wid & 3) * 32;
    const int wn = (wid >> 2) * 32;

    float acc[2][2][2][4];
    #pragma unroll
    for (int i = 0; i < 2; i++)
        #pragma unroll
        for (int g = 0; g < 2; g++)
            #pragma unroll
            for (int j = 0; j < 2; j++)
                #pragma unroll
                for (int q = 0; q < 4; q++) acc[i][g][j][q] = 0.f;

    const int a_ro  = lane & 15;
    const int a_kb  = (lane >> 4) * 16;
    const int b_ro  = (lane & 7) + (lane >> 4) * 8;
    const int b_kb  = ((lane >> 3) & 1) * 16;

    const int ar = tid >> 3, acc16 = (tid & 7) * 16;
    const size_t arow0 = (size_t)n * TSEQ;

    #pragma unroll
    for (int s = 0; s < 2; s++) {
        #pragma unroll
        for (int it = 0; it < 4; it++) {
            int r = ar + it * 32;
            CP_A16(sb + (s ? P_A_LO : P_A_HI) + SWZ(r, acc16),
                   (const char*)&g_xE[s][arow0 + r][0] + acc16);
        }
        #pragma unroll
        for (int it = 0; it < 2; it++) {
            int r = ar + it * 32;
            CP_A16(sb + (s ? P_B_LO : P_B_HI) + SWZ(r, acc16),
                   (const char*)&g_Wbf[dir][s][c0 + r][0] + acc16);
        }
    }
    CP_COMMIT();

    for (int kc = 0; kc < NCHUNK; kc++) {
        if (kc + 1 < NCHUNK) {
            const int sbase = ((kc + 1) & 1) * STAGE_SZ;
            const int kb = (kc + 1) * KC;
            #pragma unroll
            for (int s = 0; s < 2; s++) {
                #pragma unroll
                for (int it = 0; it < 4; it++) {
                    int r = ar + it * 32;
                    CP_A16(sb + sbase + (s ? P_A_LO : P_A_HI) + SWZ(r, acc16),
                           (const char*)&g_xE[s][arow0 + r][kb] + acc16);
                }
                #pragma unroll
                for (int it = 0; it < 2; it++) {
                    int r = ar + it * 32;
                    CP_A16(sb + sbase + (s ? P_B_LO : P_B_HI) + SWZ(r, acc16),
                           (const char*)&g_Wbf[dir][s][c0 + r][kb] + acc16);
                }
            }
            CP_COMMIT();
            CP_WAIT(1);
        } else {
            CP_WAIT(0);
        }
        __syncthreads();

        const uint32_t stg = sb + (kc & 1) * STAGE_SZ;
        #pragma unroll
        for (int ks = 0; ks < 4; ks++) {
            uint32_t ah[2][4], al[2][4], bh[2][4], bl[2][4];
            #pragma unroll
            for (int i = 0; i < 2; i++) {
                LDSM_X4(ah[i][0], ah[i][1], ah[i][2], ah[i][3],
                        stg + P_A_HI + SWZ(wm + i * 16 + a_ro, ks * 32 + a_kb));
                LDSM_X4(al[i][0], al[i][1], al[i][2], al[i][3],
                        stg + P_A_LO + SWZ(wm + i * 16 + a_ro, ks * 32 + a_kb));
            }
            #pragma unroll
            for (int g = 0; g < 2; g++) {
                LDSM_X4(bh[g][0], bh[g][1], bh[g][2], bh[g][3],
                        stg + P_B_HI + SWZ(wn + g * 16 + b_ro, ks * 32 + b_kb));
                LDSM_X4(bl[g][0], bl[g][1], bl[g][2], bl[g][3],
                        stg + P_B_LO + SWZ(wn + g * 16 + b_ro, ks * 32 + b_kb));
            }
            #pragma unroll
            for (int i = 0; i < 2; i++)
                #pragma unroll
                for (int g = 0; g < 2; g++)
                    #pragma unroll
                    for (int j = 0; j < 2; j++) {
                        MMA16816(acc[i][g][j], ah[i], bh[g][2 * j], bh[g][2 * j + 1]);
                        MMA16816(acc[i][g][j], ah[i], bl[g][2 * j], bl[g][2 * j + 1]);
                        MMA16816(acc[i][g][j], al[i], bh[g][2 * j], bh[g][2 * j + 1]);
                    }
        }
        if (kc + 1 < NCHUNK) __syncthreads();
    }

    #pragma unroll
    for (int i = 0; i < 2; i++)
        #pragma unroll
        for (int g = 0; g < 2; g++)
            #pragma unroll
            for (int j = 0; j < 2; j++) {
                int col = c0 + wn + g * 16 + j * 8 + (lane & 3) * 2;
                float bi0 = bias[col], bi1 = bias[col + 1];
                int r0 = wm + i * 16 + (lane >> 2);
                int r1 = r0 + 8;
                int ts0 = dir ? (TSEQ - 1 - r0) : r0;
                int ts1 = dir ? (TSEQ - 1 - r1) : r1;
                *(float2*)&g_xW[dir][ts0][n][col] =
                    make_float2(acc[i][g][j][0] + bi0, acc[i][g][j][1] + bi1);
                *(float2*)&g_xW[dir][ts1][n][col] =
                    make_float2(acc[i][g][j][2] + bi0, acc[i][g][j][3] + bi1);
            }
}

// =====================================================================
// Kernel 2: PERSISTENT recurrence (per-step grid barrier, xW prefetch,
// U-resident smem). Epilogue now uses fast __expf-based gates.
// =====================================================================
__global__ __launch_bounds__(256) void persist_step_kernel(const int* __restrict__ x)
{
    extern __shared__ char smem[];
    const uint32_t sb = smem_u32(smem);

    const int tid  = threadIdx.x;
    const int lane = tid & 31;
    const int wid  = tid >> 5;
    const int bid  = blockIdx.x;
    const int dir   = bid >> 6;
    const int mtile = (bid >> 5) & 1;
    const int ntile = bid & 31;
    const int m0  = mtile * 128;
    const int np0 = ntile * 64;
    const int ub0 = ntile * 16;

    float* zs = (float*)(smem + S2_A_OFF);          // 128x64 fp32, overlays A stage 0
    const float* xs = (const float*)(smem + S2_PF_OFF);  // xW tile [r][gate][16]

    // ---- one-time: preload U slice (hi/lo, all 8 chunks) into smem ----
    #pragma unroll
    for (int it = 0; it < 32; it++) {
        int j = tid + it * 256;
        int split = j >> 12;
        int kc    = (j >> 9) & 7;
        int row   = (j >> 3) & 63;
        int g8    = (j & 7) * 16;
        CP_A16(sb + S2_U_OFF + split * 65536 + kc * 8192 + SWZ(row, g8),
               (const char*)&g_Ubf[dir][split][np0 + row][kc * KC] + g8);
    }
    CP_COMMIT();
    CP_WAIT(0);
    __syncthreads();

    const int wm = (wid & 3) * 32;
    const int wn = (wid >> 2) * 32;
    const int a_ro  = lane & 15;
    const int a_kb  = (lane >> 4) * 16;
    const int b_ro  = (lane & 7) + (lane >> 4) * 8;
    const int b_kb  = ((lane >> 3) & 1) * 16;
    const int ar = tid >> 3, acc16 = (tid & 7) * 16;
    // xW prefetch coords: 2048 granules, 8/thread
    const int pf_r = tid >> 4, pf_seg = tid & 15;
    const int pf_gate = pf_seg >> 2, pf_q = pf_seg & 3;

    for (int t = 0; t < TSEQ; t++) {
        const int pr = t & 1, pw = pr ^ 1;

        if (t > 0) {
            float acc[2][2][2][4];
            #pragma unroll
            for (int i = 0; i < 2; i++)
                #pragma unroll
                for (int g = 0; g < 2; g++)
                    #pragma unroll
                    for (int j = 0; j < 2; j++)
                        #pragma unroll
                        for (int q = 0; q < 4; q++) acc[i][g][j][q] = 0.f;

            // ---- issue xW prefetch (no deps; retires during GEMM) ----
            #pragma unroll
            for (int it = 0; it < 8; it++) {
                int r = pf_r + it * 16;
                CP_A16(sb + S2_PF_OFF + r * 256 + pf_gate * 64 + pf_q * 16,
                       (const char*)&g_xW[dir][t][m0 + r][pf_gate * 512 + ub0] + pf_q * 16);
            }
            CP_COMMIT();

            // ---- issue A chunk 0 ----
            #pragma unroll
            for (int it = 0; it < 8; it++) {
                int j = tid + it * 256;
                int split = j >> 10;
                int r     = (j >> 3) & 127;
                int g8    = (j & 7) * 16;
                CP_A16(sb + S2_A_OFF + split * 16384 + SWZ(r, g8),
                       (const char*)&g_hbf[dir][pr][split][m0 + r][0] + g8);
            }
            CP_COMMIT();

            for (int kc = 0; kc < NCHUNK; kc++) {
                if (kc + 1 < NCHUNK) {
                    const int sbase = ((kc + 1) & 1) * 32768;
                    const int kb = (kc + 1) * KC;
                    #pragma unroll
                    for (int it = 0; it < 8; it++) {
                        int j = tid + it * 256;
                        int split = j >> 10;
                        int r     = (j >> 3) & 127;
                        int g8    = (j & 7) * 16;
                        CP_A16(sb + S2_A_OFF + sbase + split * 16384 + SWZ(r, g8),
                               (const char*)&g_hbf[dir][pr][split][m0 + r][kb] + g8);
                    }
                    CP_COMMIT();
                    CP_WAIT(1);
                } else {
                    CP_WAIT(0);
                }
                __syncthreads();

                const uint32_t sa = sb + S2_A_OFF + (kc & 1) * 32768;
                const uint32_t su = sb + S2_U_OFF + kc * 8192;
                #pragma unroll
                for (int ks = 0; ks < 4; ks++) {
                    uint32_t ah[2][4], al[2][4], bh[2][4], bl[2][4];
                    #pragma unroll
                    for (int i = 0; i < 2; i++) {
                        LDSM_X4(ah[i][0], ah[i][1], ah[i][2], ah[i][3],
                                sa + SWZ(wm + i * 16 + a_ro, ks * 32 + a_kb));
                        LDSM_X4(al[i][0], al[i][1], al[i][2], al[i][3],
                                sa + 16384 + SWZ(wm + i * 16 + a_ro, ks * 32 + a_kb));
                    }
                    #pragma unroll
                    for (int g = 0; g < 2; g++) {
                        LDSM_X4(bh[g][0], bh[g][1], bh[g][2], bh[g][3],
                                su + SWZ(wn + g * 16 + b_ro, ks * 32 + b_kb));
                        LDSM_X4(bl[g][0], bl[g][1], bl[g][2], bl[g][3],
                                su + 65536 + SWZ(wn + g * 16 + b_ro, ks * 32 + b_kb));
                    }
                    #pragma unroll
                    for (int i = 0; i < 2; i++)
                        #pragma unroll
                        for (int g = 0; g < 2; g++)
                            #pragma unroll
                            for (int j = 0; j < 2; j++) {
                                MMA16816(acc[i][g][j], ah[i], bh[g][2 * j], bh[g][2 * j + 1]);
                                MMA16816(acc[i][g][j], ah[i], bl[g][2 * j], bl[g][2 * j + 1]);
                                MMA16816(acc[i][g][j], al[i], bh[g][2 * j], bh[g][2 * j + 1]);
                            }
                }
                if (kc + 1 < NCHUNK) __syncthreads();
            }

            // write z (128x64) to smem (overlays A stage 0; chunk7 used stage 1)
            #pragma unroll
            for (int i = 0; i < 2; i++)
                #pragma unroll
                for (int g = 0; g < 2; g++)
                    #pragma unroll
                    for (int j = 0; j < 2; j++) {
                        int r = wm + i * 16 + (lane >> 2);
                        int c = wn + g * 16 + j * 8 + (lane & 3) * 2;
                        *(float2*)&zs[r * 64 + c] =
                            make_float2(acc[i][g][j][0], acc[i][g][j][1]);
                        *(float2*)&zs[(r + 8) * 64 + c] =
                            make_float2(acc[i][g][j][2], acc[i][g][j][3]);
                    }
            __syncthreads();
        } else {
            // t == 0: prefetch xW, zero z
            #pragma unroll
            for (int it = 0; it < 8; it++) {
                int r = pf_r + it * 16;
                CP_A16(sb + S2_PF_OFF + r * 256 + pf_gate * 64 + pf_q * 16,
                       (const char*)&g_xW[dir][0][m0 + r][pf_gate * 512 + ub0] + pf_q * 16);
            }
            CP_COMMIT();
            #pragma unroll
            for (int i = 0; i < 32; i++) zs[tid + i * 256] = 0.f;
            CP_WAIT(0);
            __syncthreads();
        }

        // ---- gate epilogue: 128 rows x 16 units, 8 items/thread ----
        const int tt = dir ? (TSEQ - 1 - t) : t;
        #pragma unroll
        for (int i = 0; i < 8; i++) {
            int idx = tid + i * 256;
            int r = idx >> 4, ul = idx & 15;
            int gr = m0 + r, gu = ub0 + ul;
            float4 z4 = *(const float4*)&zs[r * 64 + ul * 4];
            float zi = z4.x + xs[r * 64 + ul];
            float zf = z4.y + xs[r * 64 + 16 + ul];
            float zg = z4.z + xs[r * 64 + 32 + ul];
            float zo = z4.w + xs[r * 64 + 48 + ul];
            float ig = fsig(zi);
            float fg = fsig(zf);
            float gg = ftanh(zg);
            float og = fsig(zo);
            float cold = (t > 0) ? g_c[dir][pr][gr][gu] : 0.f;
            float cn = fg * cold + ig * gg;
            float hn = og * ftanh(cn);
            bool msk = x[gr * TSEQ + tt] != 0;

            __nv_bfloat16 oh = __float2bfloat16(0.f), ol = oh;
            if (t > 0) { oh = g_hbf[dir][pr][0][gr][gu]; ol = g_hbf[dir][pr][1][gr][gu]; }
            __nv_bfloat16 nh, nl;
            if (msk) {
                nh = __float2bfloat16(hn);
                nl = __float2bfloat16(hn - __bfloat162float(nh));
            } else { nh = oh; nl = ol; }
            g_c[dir][pw][gr][gu] = msk ? cn : cold;
            g_hbf[dir][pw][0][gr][gu] = nh;
            g_hbf[dir][pw][1][gr][gu] = nl;
        }

        // ---- grid barrier: all CTAs finish step t before step t+1 ----
        __syncthreads();
        if (tid == 0) {
            __threadfence();
            atomicAdd(&g_bar_cnt, 1u);
            const unsigned target = (unsigned)NCTA * (unsigned)(t + 1);
            while (*((volatile unsigned*)&g_bar_cnt) < target) { }
            __threadfence();
        }
        __syncthreads();
    }

    // ---- exit round: reset counter for the next graph replay ----
    if (tid == 0) {
        atomicAdd(&g_bar_cnt, 1u);
        if (bid == 0) {
            const unsigned target = (unsigned)NCTA * (unsigned)TSEQ + (unsigned)NCTA;
            while (*((volatile unsigned*)&g_bar_cnt) < target) { }
            g_bar_cnt = 0;
            __threadfence();
        }
    }
}

// =====================================================================
// Kernel 3: concat [h_fwd, h_bwd] -> out fp32 (final state in buf 0).
// =====================================================================
__global__ void copy_out_kernel(float* __restrict__ out)
{
    int i = blockIdx.x * 256 + threadIdx.x;
    int n   = i >> 10;
    int u   = i & 1023;
    int dir = u >> 9;
    int uu  = u & 511;
    out[i] = __bfloat162float(g_hbf[dir][0][0][n][uu]) +
             __bfloat162float(g_hbf[dir][0][1][n][uu]);
}

// =====================================================================
extern "C" void kernel_launch(void* const* d_in, const int* in_sizes, int n_in,
                              void* d_out, int out_size)
{
    (void)in_sizes; (void)n_in; (void)out_size;
    const int*   x    = (const int*)  d_in[0];
    const float* emb  = (const float*)d_in[1];
    const float* W_f  = (const float*)d_in[2];
    const float* U_f  = (const float*)d_in[3];
    const float* b_f  = (const float*)d_in[4];
    const float* W_b  = (const float*)d_in[5];
    const float* U_b  = (const float*)d_in[6];
    const float* b_b  = (const float*)d_in[7];
    float* out = (float*)d_out;

    cudaFuncSetAttribute(proj_mma_kernel,
        cudaFuncAttributeMaxDynamicSharedMemorySize, PIPE_SMEM);
    cudaFuncSetAttribute(persist_step_kernel,
        cudaFuncAttributeMaxDynamicSharedMemorySize, S2_SMEM);

    conv_uw_kernel<<<dim3(G4 / 32, KDIM / 32, 4), 256>>>(U_f, U_b, W_f, W_b);
    conv_e_kernel<<<NSEQ * TSEQ, 256>>>(x, emb);

    dim3 pgrid(NSEQ, G4 / 64, 2);              // (256, 32, 2)
    proj_mma_kernel<<<pgrid, 256, PIPE_SMEM>>>(b_f, b_b);

    persist_step_kernel<<<NCTA, 256, S2_SMEM>>>(x);

    copy_out_kernel<<<(NSEQ * 1024) / 256, 256>>>(out);
}

// round 17
// speedup vs baseline: 1.6651x; 1.0322x over previous
#include <cuda_runtime.h>
#include <cuda_bf16.h>
#include <math.h>
#include <stdint.h>

#define NSEQ  256     // B*S
#define TSEQ  128
#define EMBED 512
#define UNITS 512
#define G4    2048    // 4*UNITS
#define KDIM  512
#define KC    64      // k-chunk (bf16 elems) = 128B row
#define NCHUNK 8
#define NCTA  128     // persistent grid size

// ---------------- scratch (__device__ globals, allocation-free) ----------------
__device__ __align__(16) float g_xW[2][TSEQ][NSEQ][G4];               // 512 MB
__device__ __align__(16) __nv_bfloat16 g_hbf[2][2][2][NSEQ][UNITS];   // h hi/lo, dbl-buf
__device__ __align__(16) __nv_bfloat16 g_Ubf[2][2][G4][KDIM];         // U hi/lo, permuted
__device__ __align__(16) __nv_bfloat16 g_Wbf[2][2][G4][KDIM];         // W hi/lo, natural
__device__ __align__(16) __nv_bfloat16 g_xE[2][NSEQ * TSEQ][EMBED];   // emb hi/lo, 64 MB
__device__ __align__(16) float g_c[2][2][NSEQ][UNITS];
__device__ unsigned g_bar_cnt;                                        // grid barrier

// ---------------- helpers ----------------
__device__ __forceinline__ uint32_t smem_u32(const void* p) {
    uint32_t a;
    asm("{ .reg .u64 t; cvta.to.shared.u64 t, %1; cvt.u32.u64 %0, t; }" : "=r"(a) : "l"(p));
    return a;
}
__device__ __forceinline__ float fsig(float x)  { return 1.f / (1.f + __expf(-x)); }
__device__ __forceinline__ float ftanh(float x) { return 2.f / (1.f + __expf(-2.f * x)) - 1.f; }

#define SWZ(r, kb) (((r) * 128) + ((kb) ^ (((r) & 7) << 4)))

#define LDSM_X4(r0, r1, r2, r3, addr) \
    asm volatile("ldmatrix.sync.aligned.m8n8.x4.shared.b16 {%0,%1,%2,%3}, [%4];" \
        : "=r"(r0), "=r"(r1), "=r"(r2), "=r"(r3) : "r"(addr))

#define MMA16816(d, a, b0, b1) \
    asm volatile("mma.sync.aligned.m16n8k16.row.col.f32.bf16.bf16.f32 " \
        "{%0,%1,%2,%3}, {%4,%5,%6,%7}, {%8,%9}, {%0,%1,%2,%3};" \
        : "+f"((d)[0]), "+f"((d)[1]), "+f"((d)[2]), "+f"((d)[3]) \
        : "r"((a)[0]), "r"((a)[1]), "r"((a)[2]), "r"((a)[3]), "r"(b0), "r"(b1))

#define CP_A16(dst, src) \
    asm volatile("cp.async.cg.shared.global [%0], [%1], 16;" \
        :: "r"(dst), "l"(__cvta_generic_to_global(src)) : "memory")
#define CP_COMMIT() asm volatile("cp.async.commit_group;" ::: "memory")
#define CP_WAIT(n)  asm volatile("cp.async.wait_group %0;" :: "n"(n) : "memory")

// proj stage layout (48KB per stage, two stages)
#define P_A_HI 0
#define P_A_LO 16384
#define P_B_HI 32768
#define P_B_LO 40960
#define STAGE_SZ 49152
#define PIPE_SMEM (2 * STAGE_SZ)

// persistent step kernel smem:
//   U_hi resident 64KB | 3 stages x 40KB (A_hi 16K, A_lo 16K, U_lo 8K) | xW PF 32KB
#define S2_U_OFF   0
#define S2_STG_OFF 65536
#define STG_SZ     40960
#define STG_AHI    0
#define STG_ALO    16384
#define STG_ULO    32768
#define S2_PF_OFF  (S2_STG_OFF + 3 * STG_SZ)   // 188416
#define S2_SMEM    (S2_PF_OFF + 32768)         // 221184

// =====================================================================
// conv_uw: fp32 U/W -> bf16 hi/lo via 32x32 smem transpose (coalesced).
// z = dir + 2*isU. U gets gate-permuted cols (np = 4u+g); W natural.
// =====================================================================
__global__ __launch_bounds__(256) void conv_uw_kernel(
    const float* __restrict__ U_f, const float* __restrict__ U_b,
    const float* __restrict__ W_f, const float* __restrict__ W_b)
{
    __shared__ float tile[32][33];
    const int c0  = blockIdx.x * 32;
    const int k0  = blockIdx.y * 32;
    const int z   = blockIdx.z;
    const int dir = z & 1, isU = z >> 1;
    const float* __restrict__ S = isU ? (dir ? U_b : U_f) : (dir ? W_b : W_f);
    const int tid = threadIdx.x;
    const int lc = tid & 31, lk = tid >> 5;

    #pragma unroll
    for (int i = 0; i < 4; i++) {
        int k = lk + i * 8;
        tile[k][lc] = S[(size_t)(k0 + k) * G4 + c0 + lc];
    }
    __syncthreads();

    const int cl = tid >> 3;
    const int kl = (tid & 7) * 4;
    const int c  = c0 + cl;
    const int np = isU ? (4 * (c & 511) + (c >> 9)) : c;
    __nv_bfloat16* dhi = isU ? &g_Ubf[dir][0][np][k0 + kl] : &g_Wbf[dir][0][np][k0 + kl];
    __nv_bfloat16* dlo = isU ? &g_Ubf[dir][1][np][k0 + kl] : &g_Wbf[dir][1][np][k0 + kl];

    __nv_bfloat16 h4[4], l4[4];
    #pragma unroll
    for (int j = 0; j < 4; j++) {
        float v = tile[kl + j][cl];
        __nv_bfloat16 hi = __float2bfloat16(v);
        h4[j] = hi;
        l4[j] = __float2bfloat16(v - __bfloat162float(hi));
    }
    *(uint2*)dhi = *(uint2*)h4;
    *(uint2*)dlo = *(uint2*)l4;
}

// gathered embeddings -> bf16 hi/lo (dir-independent; coalesced)
__global__ void conv_e_kernel(const int* __restrict__ x,
                              const float* __restrict__ emb)
{
    const int row = blockIdx.x;               // n*TSEQ + t
    const float* src = emb + (size_t)x[row] * EMBED;
    for (int k = threadIdx.x; k < EMBED; k += blockDim.x) {
        float v = src[k];
        __nv_bfloat16 hi = __float2bfloat16(v);
        g_xE[0][row][k] = hi;
        g_xE[1][row][k] = __float2bfloat16(v - __bfloat162float(hi));
    }
}

// =====================================================================
// Kernel 1: input projection via mma.sync bf16x3 (unchanged; tensor=75%).
// =====================================================================
__global__ __launch_bounds__(256) void proj_mma_kernel(
    const float* __restrict__ b_f, const float* __restrict__ b_b)
{
    extern __shared__ char smem[];
    const uint32_t sb = smem_u32(smem);

    const int tid  = threadIdx.x;
    const int lane = tid & 31;
    const int wid  = tid >> 5;
    const int n    = blockIdx.x;
    const int c0   = blockIdx.y * 64;
    const int dir  = blockIdx.z;
    const float* __restrict__ bias = dir ? b_b : b_f;

    const int wm = (wid & 3) * 32;
    const int wn = (wid >> 2) * 32;

    float acc[2][2][2][4];
    #pragma unroll
    for (int i = 0; i < 2; i++)
        #pragma unroll
        for (int g = 0; g < 2; g++)
            #pragma unroll
            for (int j = 0; j < 2; j++)
                #pragma unroll
                for (int q = 0; q < 4; q++) acc[i][g][j][q] = 0.f;

    const int a_ro  = lane & 15;
    const int a_kb  = (lane >> 4) * 16;
    const int b_ro  = (lane & 7) + (lane >> 4) * 8;
    const int b_kb  = ((lane >> 3) & 1) * 16;

    const int ar = tid >> 3, acc16 = (tid & 7) * 16;
    const size_t arow0 = (size_t)n * TSEQ;

    #pragma unroll
    for (int s = 0; s < 2; s++) {
        #pragma unroll
        for (int it = 0; it < 4; it++) {
            int r = ar + it * 32;
            CP_A16(sb + (s ? P_A_LO : P_A_HI) + SWZ(r, acc16),
                   (const char*)&g_xE[s][arow0 + r][0] + acc16);
        }
        #pragma unroll
        for (int it = 0; it < 2; it++) {
            int r = ar + it * 32;
            CP_A16(sb + (s ? P_B_LO : P_B_HI) + SWZ(r, acc16),
                   (const char*)&g_Wbf[dir][s][c0 + r][0] + acc16);
        }
    }
    CP_COMMIT();

    for (int kc = 0; kc < NCHUNK; kc++) {
        if (kc + 1 < NCHUNK) {
            const int sbase = ((kc + 1) & 1) * STAGE_SZ;
            const int kb = (kc + 1) * KC;
            #pragma unroll
            for (int s = 0; s < 2; s++) {
                #pragma unroll
                for (int it = 0; it < 4; it++) {
                    int r = ar + it * 32;
                    CP_A16(sb + sbase + (s ? P_A_LO : P_A_HI) + SWZ(r, acc16),
                           (const char*)&g_xE[s][arow0 + r][kb] + acc16);
                }
                #pragma unroll
                for (int it = 0; it < 2; it++) {
                    int r = ar + it * 32;
                    CP_A16(sb + sbase + (s ? P_B_LO : P_B_HI) + SWZ(r, acc16),
                           (const char*)&g_Wbf[dir][s][c0 + r][kb] + acc16);
                }
            }
            CP_COMMIT();
            CP_WAIT(1);
        } else {
            CP_WAIT(0);
        }
        __syncthreads();

        const uint32_t stg = sb + (kc & 1) * STAGE_SZ;
        #pragma unroll
        for (int ks = 0; ks < 4; ks++) {
            uint32_t ah[2][4], al[2][4], bh[2][4], bl[2][4];
            #pragma unroll
            for (int i = 0; i < 2; i++) {
                LDSM_X4(ah[i][0], ah[i][1], ah[i][2], ah[i][3],
                        stg + P_A_HI + SWZ(wm + i * 16 + a_ro, ks * 32 + a_kb));
                LDSM_X4(al[i][0], al[i][1], al[i][2], al[i][3],
                        stg + P_A_LO + SWZ(wm + i * 16 + a_ro, ks * 32 + a_kb));
            }
            #pragma unroll
            for (int g = 0; g < 2; g++) {
                LDSM_X4(bh[g][0], bh[g][1], bh[g][2], bh[g][3],
                        stg + P_B_HI + SWZ(wn + g * 16 + b_ro, ks * 32 + b_kb));
                LDSM_X4(bl[g][0], bl[g][1], bl[g][2], bl[g][3],
                        stg + P_B_LO + SWZ(wn + g * 16 + b_ro, ks * 32 + b_kb));
            }
            #pragma unroll
            for (int i = 0; i < 2; i++)
                #pragma unroll
                for (int g = 0; g < 2; g++)
                    #pragma unroll
                    for (int j = 0; j < 2; j++) {
                        MMA16816(acc[i][g][j], ah[i], bh[g][2 * j], bh[g][2 * j + 1]);
                        MMA16816(acc[i][g][j], ah[i], bl[g][2 * j], bl[g][2 * j + 1]);
                        MMA16816(acc[i][g][j], al[i], bh[g][2 * j], bh[g][2 * j + 1]);
                    }
        }
        if (kc + 1 < NCHUNK) __syncthreads();
    }

    #pragma unroll
    for (int i = 0; i < 2; i++)
        #pragma unroll
        for (int g = 0; g < 2; g++)
            #pragma unroll
            for (int j = 0; j < 2; j++) {
                int col = c0 + wn + g * 16 + j * 8 + (lane & 3) * 2;
                float bi0 = bias[col], bi1 = bias[col + 1];
                int r0 = wm + i * 16 + (lane >> 2);
                int r1 = r0 + 8;
                int ts0 = dir ? (TSEQ - 1 - r0) : r0;
                int ts1 = dir ? (TSEQ - 1 - r1) : r1;
                *(float2*)&g_xW[dir][ts0][n][col] =
                    make_float2(acc[i][g][j][0] + bi0, acc[i][g][j][1] + bi1);
                *(float2*)&g_xW[dir][ts1][n][col] =
                    make_float2(acc[i][g][j][2] + bi0, acc[i][g][j][3] + bi1);
            }
}

// =====================================================================
// Kernel 2: PERSISTENT recurrence, 3-stage cp.async pipeline (2 chunks
// ahead). U_hi resident in smem; A (h hi/lo) + U_lo streamed per chunk.
// One __syncthreads per chunk. xW prefetch + per-step grid barrier.
// =====================================================================
__global__ __launch_bounds__(256) void persist_step_kernel(const int* __restrict__ x)
{
    extern __shared__ char smem[];
    const uint32_t sb = smem_u32(smem);

    const int tid  = threadIdx.x;
    const int lane = tid & 31;
    const int wid  = tid >> 5;
    const int bid  = blockIdx.x;
    const int dir   = bid >> 6;
    const int mtile = (bid >> 5) & 1;
    const int ntile = bid & 31;
    const int m0  = mtile * 128;
    const int np0 = ntile * 64;
    const int ub0 = ntile * 16;

    float* zs = (float*)(smem + S2_STG_OFF);        // 32KB z, overlays stage 0
    const float* xs = (const float*)(smem + S2_PF_OFF);

    // ---- one-time: preload U_hi slice (all 8 chunks, 64KB) ----
    #pragma unroll
    for (int it = 0; it < 16; it++) {
        int j = tid + it * 256;
        int kc  = j >> 9;
        int row = (j >> 3) & 63;
        int g8  = (j & 7) * 16;
        CP_A16(sb + S2_U_OFF + kc * 8192 + SWZ(row, g8),
               (const char*)&g_Ubf[dir][0][np0 + row][kc * KC] + g8);
    }
    CP_COMMIT();
    CP_WAIT(0);
    __syncthreads();

    const int wm = (wid & 3) * 32;
    const int wn = (wid >> 2) * 32;
    const int a_ro  = lane & 15;
    const int a_kb  = (lane >> 4) * 16;
    const int b_ro  = (lane & 7) + (lane >> 4) * 8;
    const int b_kb  = ((lane >> 3) & 1) * 16;
    // xW prefetch coords
    const int pf_r = tid >> 4, pf_seg = tid & 15;
    const int pf_gate = pf_seg >> 2, pf_q = pf_seg & 3;

    for (int t = 0; t < TSEQ; t++) {
        const int pr = t & 1, pw = pr ^ 1;

        if (t > 0) {
            float acc[2][2][2][4];
            #pragma unroll
            for (int i = 0; i < 2; i++)
                #pragma unroll
                for (int g = 0; g < 2; g++)
                    #pragma unroll
                    for (int j = 0; j < 2; j++)
                        #pragma unroll
                        for (int q = 0; q < 4; q++) acc[i][g][j][q] = 0.f;

            // ---- prologue: PF group, then chunk 0 and chunk 1 groups ----
            #pragma unroll
            for (int it = 0; it < 8; it++) {
                int r = pf_r + it * 16;
                CP_A16(sb + S2_PF_OFF + r * 256 + pf_gate * 64 + pf_q * 16,
                       (const char*)&g_xW[dir][t][m0 + r][pf_gate * 512 + ub0] + pf_q * 16);
            }
            CP_COMMIT();

            #pragma unroll
            for (int pc = 0; pc < 2; pc++) {
                const uint32_t stg = sb + S2_STG_OFF + pc * STG_SZ;
                const int kb = pc * KC;
                #pragma unroll
                for (int it = 0; it < 8; it++) {       // A hi/lo
                    int j = tid + it * 256;
                    int split = j >> 10;
                    int r     = (j >> 3) & 127;
                    int g8    = (j & 7) * 16;
                    CP_A16(stg + (split ? STG_ALO : STG_AHI) + SWZ(r, g8),
                           (const char*)&g_hbf[dir][pr][split][m0 + r][kb] + g8);
                }
                #pragma unroll
                for (int it = 0; it < 2; it++) {       // U_lo
                    int j = tid + it * 256;
                    int row = (j >> 3) & 63;
                    int g8  = (j & 7) * 16;
                    CP_A16(stg + STG_ULO + SWZ(row, g8),
                           (const char*)&g_Ubf[dir][1][np0 + row][kb] + g8);
                }
                CP_COMMIT();
            }

            #pragma unroll
            for (int kc = 0; kc < NCHUNK; kc++) {
                if (kc < NCHUNK - 1) { CP_WAIT(1); } else { CP_WAIT(0); }
                __syncthreads();

                if (kc + 2 < NCHUNK) {
                    const uint32_t stg = sb + S2_STG_OFF + ((kc + 2) % 3) * STG_SZ;
                    const int kb = (kc + 2) * KC;
                    #pragma unroll
                    for (int it = 0; it < 8; it++) {
                        int j = tid + it * 256;
                        int split = j >> 10;
                        int r     = (j >> 3) & 127;
                        int g8    = (j & 7) * 16;
                        CP_A16(stg + (split ? STG_ALO : STG_AHI) + SWZ(r, g8),
                               (const char*)&g_hbf[dir][pr][split][m0 + r][kb] + g8);
                    }
                    #pragma unroll
                    for (int it = 0; it < 2; it++) {
                        int j = tid + it * 256;
                        int row = (j >> 3) & 63;
                        int g8  = (j & 7) * 16;
                        CP_A16(stg + STG_ULO + SWZ(row, g8),
                               (const char*)&g_Ubf[dir][1][np0 + row][kb] + g8);
                    }
                    CP_COMMIT();
                }

                const uint32_t sa  = sb + S2_STG_OFF + (kc % 3) * STG_SZ;
                const uint32_t suh = sb + S2_U_OFF + kc * 8192;
                #pragma unroll
                for (int ks = 0; ks < 4; ks++) {
                    uint32_t ah[2][4], al[2][4], bh[2][4], bl[2][4];
                    #pragma unroll
                    for (int i = 0; i < 2; i++) {
                        LDSM_X4(ah[i][0], ah[i][1], ah[i][2], ah[i][3],
                                sa + STG_AHI + SWZ(wm + i * 16 + a_ro, ks * 32 + a_kb));
                        LDSM_X4(al[i][0], al[i][1], al[i][2], al[i][3],
                                sa + STG_ALO + SWZ(wm + i * 16 + a_ro, ks * 32 + a_kb));
                    }
                    #pragma unroll
                    for (int g = 0; g < 2; g++) {
                        LDSM_X4(bh[g][0], bh[g][1], bh[g][2], bh[g][3],
                                suh + SWZ(wn + g * 16 + b_ro, ks * 32 + b_kb));
                        LDSM_X4(bl[g][0], bl[g][1], bl[g][2], bl[g][3],
                                sa + STG_ULO + SWZ(wn + g * 16 + b_ro, ks * 32 + b_kb));
                    }
                    #pragma unroll
                    for (int i = 0; i < 2; i++)
                        #pragma unroll
                        for (int g = 0; g < 2; g++)
                            #pragma unroll
                            for (int j = 0; j < 2; j++) {
                                MMA16816(acc[i][g][j], ah[i], bh[g][2 * j], bh[g][2 * j + 1]);
                                MMA16816(acc[i][g][j], ah[i], bl[g][2 * j], bl[g][2 * j + 1]);
                                MMA16816(acc[i][g][j], al[i], bh[g][2 * j], bh[g][2 * j + 1]);
                            }
                }
            }

            // write z (128x64) to smem (overlays stage 0; chunk 7 used stage 1)
            #pragma unroll
            for (int i = 0; i < 2; i++)
                #pragma unroll
                for (int g = 0; g < 2; g++)
                    #pragma unroll
                    for (int j = 0; j < 2; j++) {
                        int r = wm + i * 16 + (lane >> 2);
                        int c = wn + g * 16 + j * 8 + (lane & 3) * 2;
                        *(float2*)&zs[r * 64 + c] =
                            make_float2(acc[i][g][j][0], acc[i][g][j][1]);
                        *(float2*)&zs[(r + 8) * 64 + c] =
                            make_float2(acc[i][g][j][2], acc[i][g][j][3]);
                    }
            __syncthreads();
        } else {
            // t == 0: prefetch xW, zero z
            #pragma unroll
            for (int it = 0; it < 8; it++) {
                int r = pf_r + it * 16;
                CP_A16(sb + S2_PF_OFF + r * 256 + pf_gate * 64 + pf_q * 16,
                       (const char*)&g_xW[dir][0][m0 + r][pf_gate * 512 + ub0] + pf_q * 16);
            }
            CP_COMMIT();
            #pragma unroll
            for (int i = 0; i < 32; i++) zs[tid + i * 256] = 0.f;
            CP_WAIT(0);
            __syncthreads();
        }

        // ---- gate epilogue: 128 rows x 16 units, 8 items/thread ----
        const int tt = dir ? (TSEQ - 1 - t) : t;
        #pragma unroll
        for (int i = 0; i < 8; i++) {
            int idx = tid + i * 256;
            int r = idx >> 4, ul = idx & 15;
            int gr = m0 + r, gu = ub0 + ul;
            float4 z4 = *(const float4*)&zs[r * 64 + ul * 4];
            float zi = z4.x + xs[r * 64 + ul];
            float zf = z4.y + xs[r * 64 + 16 + ul];
            float zg = z4.z + xs[r * 64 + 32 + ul];
            float zo = z4.w + xs[r * 64 + 48 + ul];
            float ig = fsig(zi);
            float fg = fsig(zf);
            float gg = ftanh(zg);
            float og = fsig(zo);
            float cold = (t > 0) ? g_c[dir][pr][gr][gu] : 0.f;
            float cn = fg * cold + ig * gg;
            float hn = og * ftanh(cn);
            bool msk = x[gr * TSEQ + tt] != 0;

            __nv_bfloat16 oh = __float2bfloat16(0.f), ol = oh;
            if (t > 0) { oh = g_hbf[dir][pr][0][gr][gu]; ol = g_hbf[dir][pr][1][gr][gu]; }
            __nv_bfloat16 nh, nl;
            if (msk) {
                nh = __float2bfloat16(hn);
                nl = __float2bfloat16(hn - __bfloat162float(nh));
            } else { nh = oh; nl = ol; }
            g_c[dir][pw][gr][gu] = msk ? cn : cold;
            g_hbf[dir][pw][0][gr][gu] = nh;
            g_hbf[dir][pw][1][gr][gu] = nl;
        }

        // ---- grid barrier: all CTAs finish step t before step t+1 ----
        __syncthreads();
        if (tid == 0) {
            __threadfence();
            atomicAdd(&g_bar_cnt, 1u);
            const unsigned target = (unsigned)NCTA * (unsigned)(t + 1);
            while (*((volatile unsigned*)&g_bar_cnt) < target) { }
            __threadfence();
        }
        __syncthreads();
    }

    // ---- exit round: reset counter for the next graph replay ----
    if (tid == 0) {
        atomicAdd(&g_bar_cnt, 1u);
        if (bid == 0) {
            const unsigned target = (unsigned)NCTA * (unsigned)TSEQ + (unsigned)NCTA;
            while (*((volatile unsigned*)&g_bar_cnt) < target) { }
            g_bar_cnt = 0;
            __threadfence();
        }
    }
}

// =====================================================================
// Kernel 3: concat [h_fwd, h_bwd] -> out fp32 (final state in buf 0).
// =====================================================================
__global__ void copy_out_kernel(float* __restrict__ out)
{
    int i = blockIdx.x * 256 + threadIdx.x;
    int n   = i >> 10;
    int u   = i & 1023;
    int dir = u >> 9;
    int uu  = u & 511;
    out[i] = __bfloat162float(g_hbf[dir][0][0][n][uu]) +
             __bfloat162float(g_hbf[dir][0][1][n][uu]);
}

// =====================================================================
extern "C" void kernel_launch(void* const* d_in, const int* in_sizes, int n_in,
                              void* d_out, int out_size)
{
    (void)in_sizes; (void)n_in; (void)out_size;
    const int*   x    = (const int*)  d_in[0];
    const float* emb  = (const float*)d_in[1];
    const float* W_f  = (const float*)d_in[2];
    const float* U_f  = (const float*)d_in[3];
    const float* b_f  = (const float*)d_in[4];
    const float* W_b  = (const float*)d_in[5];
    const float* U_b  = (const float*)d_in[6];
    const float* b_b  = (const float*)d_in[7];
    float* out = (float*)d_out;

    cudaFuncSetAttribute(proj_mma_kernel,
        cudaFuncAttributeMaxDynamicSharedMemorySize, PIPE_SMEM);
    cudaFuncSetAttribute(persist_step_kernel,
        cudaFuncAttributeMaxDynamicSharedMemorySize, S2_SMEM);

    conv_uw_kernel<<<dim3(G4 / 32, KDIM / 32, 4), 256>>>(U_f, U_b, W_f, W_b);
    conv_e_kernel<<<NSEQ * TSEQ, 256>>>(x, emb);

    dim3 pgrid(NSEQ, G4 / 64, 2);              // (256, 32, 2)
    proj_mma_kernel<<<pgrid, 256, PIPE_SMEM>>>(b_f, b_b);

    persist_step_kernel<<<NCTA, 256, S2_SMEM>>>(x);

    copy_out_kernel<<<(NSEQ * 1024) / 256, 256>>>(out);
}